// round 3
// baseline (speedup 1.0000x reference)
#include <cuda_runtime.h>
#include <cuda_fp16.h>
#include <cuda_bf16.h>
#include <cstdint>

#define N_NODES 51200
#define N_EDGES 2048000
#define F_IN    400
#define F_HID   128
#define RO_OUT  8
#define N_GRAPHS 128
#define FC1_IN  3200
#define FC1_OUT 400
#define BN_EPS  1e-5f
#define SCAN_BLOCKS 50   // 50 * 1024 = 51200

// ---------------- device scratch (static, allocation-free) ----------------
__device__ __half g_h16[(size_t)N_NODES * F_HID];   // GEMM output, fp16 for cheap gathers
__device__ float  g_bufB[(size_t)N_NODES * F_HID];  // agg1 output (fp32, feeds GEMM2)
__device__ float g_deg[N_NODES];
__device__ float g_dinv[N_NODES];
__device__ int   g_cnt[N_NODES];
__device__ int   g_off[N_NODES + 1];
__device__ int   g_ptr[N_NODES];
__device__ int   g_part[SCAN_BLOCKS];
__device__ int   g_partoff[SCAN_BLOCKS];
__device__ int   g_erow[N_EDGES];
__device__ float g_enorm[N_EDGES];
__device__ float g_feats[(size_t)N_NODES * RO_OUT];
__device__ float g_z[N_GRAPHS * FC1_OUT];
__device__ float g_mu[FC1_OUT];
__device__ float g_rstd[FC1_OUT];

__device__ __forceinline__ float mishf(float x) {
    float sp = fmaxf(x, 0.0f) + log1pf(expf(-fabsf(x)));
    return x * tanhf(sp);
}

// ---------------- graph preprocessing ----------------
__global__ void k_init_deg_cnt() {
    int i = blockIdx.x * blockDim.x + threadIdx.x;
    if (i < N_NODES) { g_deg[i] = 1.0f; g_cnt[i] = 0; }   // self-loop weight 1
}

__global__ void k_edge_pass1(const int* __restrict__ col, const float* __restrict__ ew) {
    int e = blockIdx.x * blockDim.x + threadIdx.x;
    if (e < N_EDGES) {
        int c = col[e];
        atomicAdd(&g_deg[c], ew[e]);
        atomicAdd(&g_cnt[c], 1);
    }
}

// phase 1: per-1024-chunk reduction of g_cnt + dinv computation (fused)
__global__ __launch_bounds__(1024) void k_part_dinv() {
    int b = blockIdx.x, t = threadIdx.x;
    int i = b * 1024 + t;
    float d = g_deg[i];
    g_dinv[i] = (d > 0.0f) ? rsqrtf(d) : 0.0f;
    int v = g_cnt[i];
    #pragma unroll
    for (int dlt = 16; dlt > 0; dlt >>= 1) v += __shfl_down_sync(~0u, v, dlt);
    __shared__ int ws[32];
    if ((t & 31) == 0) ws[t >> 5] = v;
    __syncthreads();
    if (t < 32) {
        int x = ws[t];
        #pragma unroll
        for (int dlt = 16; dlt > 0; dlt >>= 1) x += __shfl_down_sync(~0u, x, dlt);
        if (t == 0) g_part[b] = x;
    }
}

// phase 2: exclusive scan of 50 partials
__global__ void k_scan_part() {
    if (threadIdx.x == 0) {
        int run = 0;
        for (int b = 0; b < SCAN_BLOCKS; ++b) {
            g_partoff[b] = run;
            run += g_part[b];
        }
        g_off[N_NODES] = run;
    }
}

// phase 3: per-block exclusive scan + add partial offset
__global__ __launch_bounds__(1024) void k_scan_blocks() {
    int b = blockIdx.x, t = threadIdx.x;
    int i = b * 1024 + t;
    int v = g_cnt[i];
    int lane = t & 31, w = t >> 5;
    int x = v;
    #pragma unroll
    for (int dlt = 1; dlt < 32; dlt <<= 1) {
        int y = __shfl_up_sync(~0u, x, dlt);
        if (lane >= dlt) x += y;
    }
    __shared__ int ws[32];
    if (lane == 31) ws[w] = x;
    __syncthreads();
    if (w == 0) {
        int y = ws[lane];
        #pragma unroll
        for (int dlt = 1; dlt < 32; dlt <<= 1) {
            int z = __shfl_up_sync(~0u, y, dlt);
            if (lane >= dlt) y += z;
        }
        ws[lane] = y;
    }
    __syncthreads();
    int incl = x + (w > 0 ? ws[w - 1] : 0);
    int excl = incl - v + g_partoff[b];
    g_off[i] = excl;
    g_ptr[i] = excl;
}

__global__ void k_edge_pass2(const int* __restrict__ row, const int* __restrict__ col,
                             const float* __restrict__ ew) {
    int e = blockIdx.x * blockDim.x + threadIdx.x;
    if (e < N_EDGES) {
        int r = row[e], c = col[e];
        float nrm = g_dinv[r] * ew[e] * g_dinv[c];
        int p = atomicAdd(&g_ptr[c], 1);
        g_erow[p] = r;
        g_enorm[p] = nrm;
    }
}

// ---------------- SGEMM: C[M,128](fp16) = A[M,K](fp32) @ B[K,128], fp32 accum ----------------
__global__ __launch_bounds__(256) void k_sgemm_h(const float* __restrict__ A,
                                                 const float* __restrict__ B,
                                                 __half* __restrict__ C, int K) {
    __shared__ float As[8][128];
    __shared__ float Bs[8][128];
    int tid = threadIdx.x;
    int row0 = blockIdx.x * 128;
    int ty = tid >> 4, tx = tid & 15;
    int ar = tid >> 1;
    int ak = (tid & 1) * 4;
    int br = tid >> 5;
    int bc = (tid & 31) * 4;

    float acc[8][8];
    #pragma unroll
    for (int i = 0; i < 8; ++i)
        #pragma unroll
        for (int j = 0; j < 8; ++j) acc[i][j] = 0.0f;

    for (int k0 = 0; k0 < K; k0 += 8) {
        float4 av = *reinterpret_cast<const float4*>(&A[(size_t)(row0 + ar) * K + k0 + ak]);
        float4 bv = *reinterpret_cast<const float4*>(&B[(size_t)(k0 + br) * 128 + bc]);
        As[ak + 0][ar] = av.x; As[ak + 1][ar] = av.y;
        As[ak + 2][ar] = av.z; As[ak + 3][ar] = av.w;
        *reinterpret_cast<float4*>(&Bs[br][bc]) = bv;
        __syncthreads();
        #pragma unroll
        for (int kk = 0; kk < 8; ++kk) {
            float a[8], b[8];
            #pragma unroll
            for (int i = 0; i < 8; ++i) a[i] = As[kk][ty * 8 + i];
            #pragma unroll
            for (int j = 0; j < 8; ++j) b[j] = Bs[kk][tx * 8 + j];
            #pragma unroll
            for (int i = 0; i < 8; ++i)
                #pragma unroll
                for (int j = 0; j < 8; ++j)
                    acc[i][j] = fmaf(a[i], b[j], acc[i][j]);
        }
        __syncthreads();
    }
    #pragma unroll
    for (int i = 0; i < 8; ++i) {
        __half2 hv[4];
        #pragma unroll
        for (int j = 0; j < 4; ++j)
            hv[j] = __floats2half2_rn(acc[i][2 * j], acc[i][2 * j + 1]);
        *reinterpret_cast<uint4*>(&C[(size_t)(row0 + ty * 8 + i) * 128 + tx * 8]) =
            *reinterpret_cast<uint4*>(hv);
    }
}

// ---------------- warp-per-node aggregation core ----------------
// lane l owns features [4l, 4l+4): one uint2 (4 halfs) per gather.
struct Acc4 { float a0, a1, a2, a3; };

__device__ __forceinline__ Acc4 agg_node(int i, const __half* __restrict__ h, int lane) {
    const uint2* hp = reinterpret_cast<const uint2*>(h);
    float di = g_dinv[i];
    float w0 = di * di;
    uint2 sv = hp[(size_t)i * 32 + lane];
    float2 sa = __half22float2(*reinterpret_cast<__half2*>(&sv.x));
    float2 sb = __half22float2(*reinterpret_cast<__half2*>(&sv.y));
    Acc4 acc = { w0 * sa.x, w0 * sa.y, w0 * sb.x, w0 * sb.y };
    int e0 = g_off[i], e1 = g_off[i + 1];
    for (int base = e0; base < e1; base += 32) {
        int n = min(32, e1 - base);
        int r = 0; float nr = 0.0f;
        if (lane < n) { r = g_erow[base + lane]; nr = g_enorm[base + lane]; }
        #pragma unroll 4
        for (int j = 0; j < n; ++j) {
            int   rj = __shfl_sync(~0u, r, j);
            float nj = __shfl_sync(~0u, nr, j);
            uint2 v = hp[(size_t)rj * 32 + lane];
            float2 x = __half22float2(*reinterpret_cast<__half2*>(&v.x));
            float2 y = __half22float2(*reinterpret_cast<__half2*>(&v.y));
            acc.a0 = fmaf(nj, x.x, acc.a0);
            acc.a1 = fmaf(nj, x.y, acc.a1);
            acc.a2 = fmaf(nj, y.x, acc.a2);
            acc.a3 = fmaf(nj, y.y, acc.a3);
        }
    }
    return acc;
}

// agg1: out(fp32) = mish(agg + bias)   [feeds GEMM2]
__global__ __launch_bounds__(256) void k_agg1(const __half* __restrict__ h,
                                              const float* __restrict__ bias,
                                              float* __restrict__ out) {
    int lane = threadIdx.x & 31;
    int i = blockIdx.x * 8 + (threadIdx.x >> 5);
    Acc4 acc = agg_node(i, h, lane);
    float4 bb = *reinterpret_cast<const float4*>(&bias[lane * 4]);
    float4 o;
    o.x = mishf(acc.a0 + bb.x);
    o.y = mishf(acc.a1 + bb.y);
    o.z = mishf(acc.a2 + bb.z);
    o.w = mishf(acc.a3 + bb.w);
    *reinterpret_cast<float4*>(&out[(size_t)i * 128 + lane * 4]) = o;
}

// agg2 fused with readout: feats[i, 0..7] = mish( mish(agg+b2) @ ro_w + ro_b )
__global__ __launch_bounds__(256) void k_agg2_readout(const __half* __restrict__ h,
                                                      const float* __restrict__ bias,
                                                      const float* __restrict__ ro_w,
                                                      const float* __restrict__ ro_b) {
    int lane = threadIdx.x & 31;
    int i = blockIdx.x * 8 + (threadIdx.x >> 5);
    Acc4 acc = agg_node(i, h, lane);
    float4 bb = *reinterpret_cast<const float4*>(&bias[lane * 4]);
    float m0 = mishf(acc.a0 + bb.x);
    float m1 = mishf(acc.a1 + bb.y);
    float m2 = mishf(acc.a2 + bb.z);
    float m3 = mishf(acc.a3 + bb.w);
    int f = lane * 4;
    float res = 0.0f;
    #pragma unroll
    for (int j = 0; j < 8; ++j) {
        float p = m0 * __ldg(&ro_w[(f + 0) * 8 + j])
                + m1 * __ldg(&ro_w[(f + 1) * 8 + j])
                + m2 * __ldg(&ro_w[(f + 2) * 8 + j])
                + m3 * __ldg(&ro_w[(f + 3) * 8 + j]);
        #pragma unroll
        for (int d = 16; d > 0; d >>= 1) p += __shfl_xor_sync(~0u, p, d);
        if (lane == j) res = p;
    }
    if (lane < 8)
        g_feats[(size_t)i * 8 + lane] = mishf(res + __ldg(&ro_b[lane]));
}

// ---------------- fc1: 2 graphs per block ----------------
__global__ __launch_bounds__(400) void k_fc1(const float* __restrict__ W,
                                             const float* __restrict__ b) {
    int g0 = blockIdx.x * 2;
    int c = threadIdx.x;
    __shared__ float s0[FC1_IN], s1[FC1_IN];
    for (int k = c; k < FC1_IN; k += FC1_OUT) {
        s0[k] = g_feats[(size_t)g0 * FC1_IN + k];
        s1[k] = g_feats[(size_t)(g0 + 1) * FC1_IN + k];
    }
    __syncthreads();
    float a0 = b[c], a1 = a0;
    #pragma unroll 4
    for (int k = 0; k < FC1_IN; ++k) {
        float w = W[(size_t)k * FC1_OUT + c];
        a0 = fmaf(s0[k], w, a0);
        a1 = fmaf(s1[k], w, a1);
    }
    g_z[g0 * FC1_OUT + c] = a0;
    g_z[(g0 + 1) * FC1_OUT + c] = a1;
}

// ---------------- batchnorm stats ----------------
__global__ void k_bn_stats() {
    int c = blockIdx.x * blockDim.x + threadIdx.x;
    if (c >= FC1_OUT) return;
    float s = 0.0f;
    for (int r = 0; r < N_GRAPHS; ++r) s += g_z[r * FC1_OUT + c];
    float m = s * (1.0f / N_GRAPHS);
    float v = 0.0f;
    for (int r = 0; r < N_GRAPHS; ++r) {
        float d = g_z[r * FC1_OUT + c] - m;
        v = fmaf(d, d, v);
    }
    v *= (1.0f / N_GRAPHS);
    g_mu[c] = m;
    g_rstd[c] = rsqrtf(v + BN_EPS);
}

// ---------------- final head ----------------
__global__ __launch_bounds__(512) void k_final(const float* __restrict__ gamma,
                                               const float* __restrict__ beta,
                                               const float* __restrict__ w2,
                                               const float* __restrict__ b2,
                                               float* __restrict__ out) {
    int g = blockIdx.x;
    int t = threadIdx.x;
    __shared__ float s0[512], s1[512];
    float v0 = 0.0f, v1 = 0.0f;
    if (t < FC1_OUT) {
        float zn = (g_z[g * FC1_OUT + t] - g_mu[t]) * g_rstd[t] * gamma[t] + beta[t];
        float m = mishf(zn);
        v0 = m * w2[t * 2 + 0];
        v1 = m * w2[t * 2 + 1];
    }
    s0[t] = v0; s1[t] = v1;
    __syncthreads();
    for (int d = 256; d > 0; d >>= 1) {
        if (t < d) { s0[t] += s0[t + d]; s1[t] += s1[t + d]; }
        __syncthreads();
    }
    if (t == 0) {
        out[g * 2 + 0] = s0[0] + b2[0];
        out[g * 2 + 1] = s1[0] + b2[1];
    }
}

// ---------------- host launcher ----------------
extern "C" void kernel_launch(void* const* d_in, const int* in_sizes, int n_in,
                              void* d_out, int out_size) {
    const float* x      = (const float*)d_in[0];
    const int*   ei     = (const int*)d_in[1];
    const float* ea     = (const float*)d_in[2];
    const float* w1     = (const float*)d_in[4];
    const float* b1     = (const float*)d_in[5];
    const float* w2     = (const float*)d_in[6];
    const float* b2     = (const float*)d_in[7];
    const float* ro_w   = (const float*)d_in[8];
    const float* ro_b   = (const float*)d_in[9];
    const float* fc1_w  = (const float*)d_in[10];
    const float* fc1_b  = (const float*)d_in[11];
    const float* gamma  = (const float*)d_in[12];
    const float* beta   = (const float*)d_in[13];
    const float* fc2_w  = (const float*)d_in[14];
    const float* fc2_b  = (const float*)d_in[15];
    float* out = (float*)d_out;

    const int* row = ei;
    const int* col = ei + N_EDGES;

    __half* pH = nullptr;
    float*  pB = nullptr;
    cudaGetSymbolAddress((void**)&pH, g_h16);
    cudaGetSymbolAddress((void**)&pB, g_bufB);

    static cudaStream_t s2 = nullptr;
    static cudaEvent_t evFork = nullptr, evJoin = nullptr;
    if (!s2) {
        cudaStreamCreateWithFlags(&s2, cudaStreamNonBlocking);
        cudaEventCreateWithFlags(&evFork, cudaEventDisableTiming);
        cudaEventCreateWithFlags(&evJoin, cudaEventDisableTiming);
    }

    // fork: preprocessing on s2 hides under GEMM1 on the main stream
    cudaEventRecord(evFork, 0);
    cudaStreamWaitEvent(s2, evFork, 0);

    k_init_deg_cnt<<<(N_NODES + 255) / 256, 256, 0, s2>>>();
    k_edge_pass1<<<(N_EDGES + 255) / 256, 256, 0, s2>>>(col, ea);
    k_part_dinv<<<SCAN_BLOCKS, 1024, 0, s2>>>();
    k_scan_part<<<1, 32, 0, s2>>>();
    k_scan_blocks<<<SCAN_BLOCKS, 1024, 0, s2>>>();
    k_edge_pass2<<<(N_EDGES + 255) / 256, 256, 0, s2>>>(row, col, ea);
    cudaEventRecord(evJoin, s2);

    // GEMM1 (concurrent with preprocessing)
    k_sgemm_h<<<N_NODES / 128, 256>>>(x, w1, pH, F_IN);

    cudaStreamWaitEvent(0, evJoin, 0);

    // conv1 aggregation -> fp32 bufB; conv2 GEMM -> fp16; agg2 fused with readout
    k_agg1<<<N_NODES / 8, 256>>>(pH, b1, pB);
    k_sgemm_h<<<N_NODES / 128, 256>>>(pB, w2, pH, F_HID);
    k_agg2_readout<<<N_NODES / 8, 256>>>(pH, b2, ro_w, ro_b);

    // fc1 -> z [128, 400]
    k_fc1<<<N_GRAPHS / 2, FC1_OUT>>>(fc1_w, fc1_b);

    // batchnorm stats + final head
    k_bn_stats<<<2, 256>>>();
    k_final<<<N_GRAPHS, 512>>>(gamma, beta, fc2_w, fc2_b, out);
}

// round 4
// speedup vs baseline: 1.2199x; 1.2199x over previous
#include <cuda_runtime.h>
#include <cuda_fp16.h>
#include <cuda_bf16.h>
#include <mma.h>
#include <cstdint>

using namespace nvcuda;

#define N_NODES 51200
#define N_EDGES 2048000
#define F_IN    400
#define F_HID   128
#define RO_OUT  8
#define N_GRAPHS 128
#define FC1_IN  3200
#define FC1_OUT 400
#define BN_EPS  1e-5f
#define SCAN_BLOCKS 50

// ---------------- device scratch (static, allocation-free) ----------------
__device__ __half g_h16[(size_t)N_NODES * F_HID];   // GEMM output (fp16 for cheap gathers)
__device__ float  g_bufB[(size_t)N_NODES * F_HID];  // agg1 output (fp32, feeds GEMM2)
__device__ float g_deg[N_NODES];
__device__ float g_dinv[N_NODES];
__device__ int   g_cnt[N_NODES];
__device__ int   g_off[N_NODES + 1];
__device__ int   g_ptr[N_NODES];
__device__ int   g_part[SCAN_BLOCKS];
__device__ int   g_partoff[SCAN_BLOCKS];
__device__ int   g_erow[N_EDGES];
__device__ float g_enorm[N_EDGES];
__device__ float g_feats[(size_t)N_NODES * RO_OUT];
__device__ float g_z[N_GRAPHS * FC1_OUT];
__device__ float g_mu[FC1_OUT];
__device__ float g_rstd[FC1_OUT];

__device__ __forceinline__ float mishf(float x) {
    float sp = fmaxf(x, 0.0f) + log1pf(expf(-fabsf(x)));
    return x * tanhf(sp);
}

// ---------------- graph preprocessing ----------------
__global__ void k_init_deg_cnt() {
    int i = blockIdx.x * blockDim.x + threadIdx.x;
    if (i < N_NODES) { g_deg[i] = 1.0f; g_cnt[i] = 0; }
}

__global__ void k_edge_pass1(const int* __restrict__ col, const float* __restrict__ ew) {
    int e = blockIdx.x * blockDim.x + threadIdx.x;
    if (e < N_EDGES) {
        int c = col[e];
        atomicAdd(&g_deg[c], ew[e]);
        atomicAdd(&g_cnt[c], 1);
    }
}

__global__ __launch_bounds__(1024) void k_part_dinv() {
    int b = blockIdx.x, t = threadIdx.x;
    int i = b * 1024 + t;
    float d = g_deg[i];
    g_dinv[i] = (d > 0.0f) ? rsqrtf(d) : 0.0f;
    int v = g_cnt[i];
    #pragma unroll
    for (int dlt = 16; dlt > 0; dlt >>= 1) v += __shfl_down_sync(~0u, v, dlt);
    __shared__ int ws[32];
    if ((t & 31) == 0) ws[t >> 5] = v;
    __syncthreads();
    if (t < 32) {
        int x = ws[t];
        #pragma unroll
        for (int dlt = 16; dlt > 0; dlt >>= 1) x += __shfl_down_sync(~0u, x, dlt);
        if (t == 0) g_part[b] = x;
    }
}

__global__ void k_scan_part() {
    if (threadIdx.x == 0) {
        int run = 0;
        for (int b = 0; b < SCAN_BLOCKS; ++b) {
            g_partoff[b] = run;
            run += g_part[b];
        }
        g_off[N_NODES] = run;
    }
}

__global__ __launch_bounds__(1024) void k_scan_blocks() {
    int b = blockIdx.x, t = threadIdx.x;
    int i = b * 1024 + t;
    int v = g_cnt[i];
    int lane = t & 31, w = t >> 5;
    int x = v;
    #pragma unroll
    for (int dlt = 1; dlt < 32; dlt <<= 1) {
        int y = __shfl_up_sync(~0u, x, dlt);
        if (lane >= dlt) x += y;
    }
    __shared__ int ws[32];
    if (lane == 31) ws[w] = x;
    __syncthreads();
    if (w == 0) {
        int y = ws[lane];
        #pragma unroll
        for (int dlt = 1; dlt < 32; dlt <<= 1) {
            int z = __shfl_up_sync(~0u, y, dlt);
            if (lane >= dlt) y += z;
        }
        ws[lane] = y;
    }
    __syncthreads();
    int incl = x + (w > 0 ? ws[w - 1] : 0);
    int excl = incl - v + g_partoff[b];
    g_off[i] = excl;
    g_ptr[i] = excl;
}

__global__ void k_edge_pass2(const int* __restrict__ row, const int* __restrict__ col,
                             const float* __restrict__ ew) {
    int e = blockIdx.x * blockDim.x + threadIdx.x;
    if (e < N_EDGES) {
        int r = row[e], c = col[e];
        float nrm = g_dinv[r] * ew[e] * g_dinv[c];
        int p = atomicAdd(&g_ptr[c], 1);
        g_erow[p] = r;
        g_enorm[p] = nrm;
    }
}

// ---------------- bf16-split tensor-core GEMM ----------------
// C16[M,128] = A[M,K] @ B[K,128];  A,B fp32 in, split to bf16 hi/lo on the fly.
// 3 passes: hi*hi + hi*lo + lo*hi -> ~fp32 accuracy. Output fp16.
#define A_LD 24
#define B_LD 136
#define SM_AHI 0
#define SM_ALO (128 * A_LD * 2)                 // 6144
#define SM_BHI (SM_ALO + 128 * A_LD * 2)        // 12288
#define SM_BLO (SM_BHI + 16 * B_LD * 2)         // 16640
#define SM_TOT (SM_BLO + 16 * B_LD * 2)         // 20992

__global__ __launch_bounds__(256) void k_gemm_bf16(const float* __restrict__ A,
                                                   const float* __restrict__ B,
                                                   __half* __restrict__ C, int K) {
    __shared__ __align__(16) char smem_raw[SM_TOT];
    __nv_bfloat16* Ahi = reinterpret_cast<__nv_bfloat16*>(smem_raw + SM_AHI);
    __nv_bfloat16* Alo = reinterpret_cast<__nv_bfloat16*>(smem_raw + SM_ALO);
    __nv_bfloat16* Bhi = reinterpret_cast<__nv_bfloat16*>(smem_raw + SM_BHI);
    __nv_bfloat16* Blo = reinterpret_cast<__nv_bfloat16*>(smem_raw + SM_BLO);

    int tid = threadIdx.x;
    int lane = tid & 31;
    int w = tid >> 5;           // 0..7
    int wm = w & 1;             // warp row (64 rows)
    int wn = w >> 1;            // warp col (32 cols)
    int row0 = blockIdx.x * 128;

    wmma::fragment<wmma::accumulator, 16, 16, 16, float> acc[4][2];
    #pragma unroll
    for (int i = 0; i < 4; ++i)
        #pragma unroll
        for (int j = 0; j < 2; ++j) wmma::fill_fragment(acc[i][j], 0.0f);

    for (int k0 = 0; k0 < K; k0 += 16) {
        // load + split A tile [128][16]
        #pragma unroll
        for (int c = 0; c < 2; ++c) {
            int idx = tid + c * 256;
            int ar = idx >> 2, kq = (idx & 3) * 4;
            float4 v = *reinterpret_cast<const float4*>(&A[(size_t)(row0 + ar) * K + k0 + kq]);
            __nv_bfloat16 hx = __float2bfloat16_rn(v.x);
            __nv_bfloat16 hy = __float2bfloat16_rn(v.y);
            __nv_bfloat16 hz = __float2bfloat16_rn(v.z);
            __nv_bfloat16 hw = __float2bfloat16_rn(v.w);
            __nv_bfloat162 h0; h0.x = hx; h0.y = hy;
            __nv_bfloat162 h1; h1.x = hz; h1.y = hw;
            __nv_bfloat162 l0; l0.x = __float2bfloat16_rn(v.x - __bfloat162float(hx));
                               l0.y = __float2bfloat16_rn(v.y - __bfloat162float(hy));
            __nv_bfloat162 l1; l1.x = __float2bfloat16_rn(v.z - __bfloat162float(hz));
                               l1.y = __float2bfloat16_rn(v.w - __bfloat162float(hw));
            __nv_bfloat16* ph = &Ahi[ar * A_LD + kq];
            __nv_bfloat16* pl = &Alo[ar * A_LD + kq];
            *reinterpret_cast<__nv_bfloat162*>(ph)     = h0;
            *reinterpret_cast<__nv_bfloat162*>(ph + 2) = h1;
            *reinterpret_cast<__nv_bfloat162*>(pl)     = l0;
            *reinterpret_cast<__nv_bfloat162*>(pl + 2) = l1;
        }
        // load + split B tile [16][128]
        #pragma unroll
        for (int c = 0; c < 2; ++c) {
            int idx = tid + c * 256;
            int kr = idx >> 5, cq = (idx & 31) * 4;
            float4 v = *reinterpret_cast<const float4*>(&B[(size_t)(k0 + kr) * 128 + cq]);
            __nv_bfloat16 hx = __float2bfloat16_rn(v.x);
            __nv_bfloat16 hy = __float2bfloat16_rn(v.y);
            __nv_bfloat16 hz = __float2bfloat16_rn(v.z);
            __nv_bfloat16 hw = __float2bfloat16_rn(v.w);
            __nv_bfloat162 h0; h0.x = hx; h0.y = hy;
            __nv_bfloat162 h1; h1.x = hz; h1.y = hw;
            __nv_bfloat162 l0; l0.x = __float2bfloat16_rn(v.x - __bfloat162float(hx));
                               l0.y = __float2bfloat16_rn(v.y - __bfloat162float(hy));
            __nv_bfloat162 l1; l1.x = __float2bfloat16_rn(v.z - __bfloat162float(hz));
                               l1.y = __float2bfloat16_rn(v.w - __bfloat162float(hw));
            __nv_bfloat16* ph = &Bhi[kr * B_LD + cq];
            __nv_bfloat16* pl = &Blo[kr * B_LD + cq];
            *reinterpret_cast<__nv_bfloat162*>(ph)     = h0;
            *reinterpret_cast<__nv_bfloat162*>(ph + 2) = h1;
            *reinterpret_cast<__nv_bfloat162*>(pl)     = l0;
            *reinterpret_cast<__nv_bfloat162*>(pl + 2) = l1;
        }
        __syncthreads();

        wmma::fragment<wmma::matrix_b, 16, 16, 16, __nv_bfloat16, wmma::row_major> bh[2], bl[2];
        #pragma unroll
        for (int j = 0; j < 2; ++j) {
            wmma::load_matrix_sync(bh[j], &Bhi[wn * 32 + j * 16], B_LD);
            wmma::load_matrix_sync(bl[j], &Blo[wn * 32 + j * 16], B_LD);
        }
        wmma::fragment<wmma::matrix_a, 16, 16, 16, __nv_bfloat16, wmma::row_major> af[4];
        #pragma unroll
        for (int i = 0; i < 4; ++i)
            wmma::load_matrix_sync(af[i], &Ahi[(wm * 64 + i * 16) * A_LD], A_LD);
        #pragma unroll
        for (int i = 0; i < 4; ++i)
            #pragma unroll
            for (int j = 0; j < 2; ++j) {
                wmma::mma_sync(acc[i][j], af[i], bh[j], acc[i][j]);
                wmma::mma_sync(acc[i][j], af[i], bl[j], acc[i][j]);
            }
        #pragma unroll
        for (int i = 0; i < 4; ++i)
            wmma::load_matrix_sync(af[i], &Alo[(wm * 64 + i * 16) * A_LD], A_LD);
        #pragma unroll
        for (int i = 0; i < 4; ++i)
            #pragma unroll
            for (int j = 0; j < 2; ++j)
                wmma::mma_sync(acc[i][j], af[i], bh[j], acc[i][j]);
        __syncthreads();
    }

    // epilogue: stage each 16x16 frag in smem (reused), emit fp16
    float* stage = reinterpret_cast<float*>(smem_raw) + w * 16 * 20;
    int r = lane >> 1, c0 = (lane & 1) * 8;
    #pragma unroll
    for (int i = 0; i < 4; ++i)
        #pragma unroll
        for (int j = 0; j < 2; ++j) {
            wmma::store_matrix_sync(stage, acc[i][j], 20, wmma::mem_row_major);
            __syncwarp();
            const float* sp = stage + r * 20 + c0;
            __half2 o[4];
            #pragma unroll
            for (int q = 0; q < 4; ++q) o[q] = __floats2half2_rn(sp[2 * q], sp[2 * q + 1]);
            size_t grow = (size_t)(row0 + wm * 64 + i * 16 + r);
            int gcol = wn * 32 + j * 16 + c0;
            *reinterpret_cast<uint4*>(&C[grow * 128 + gcol]) = *reinterpret_cast<uint4*>(o);
            __syncwarp();
        }
}

// ---------------- agg1 (block-per-node, fp16 gathers): out(fp32) = mish(agg + b) ----------------
__global__ __launch_bounds__(128) void k_agg1(const __half* __restrict__ h,
                                              const float* __restrict__ bias,
                                              float* __restrict__ out) {
    int i = blockIdx.x;
    int f = threadIdx.x;
    __shared__ int   s_row[128];
    __shared__ float s_nrm[128];
    float di = g_dinv[i];
    float acc = di * di * __half2float(h[(size_t)i * 128 + f]);
    int e0 = g_off[i], e1 = g_off[i + 1];
    for (int base = e0; base < e1; base += 128) {
        int n = min(128, e1 - base);
        if (f < n) { s_row[f] = g_erow[base + f]; s_nrm[f] = g_enorm[base + f]; }
        __syncthreads();
        #pragma unroll 4
        for (int j = 0; j < n; ++j)
            acc = fmaf(s_nrm[j], __half2float(h[(size_t)s_row[j] * 128 + f]), acc);
        __syncthreads();
    }
    out[(size_t)i * 128 + f] = mishf(acc + bias[f]);
}

// ---------------- agg2 + readout fused: feats = mish( mish(agg+b) @ ro_w + ro_b ) ----------------
__global__ __launch_bounds__(128) void k_agg2ro(const __half* __restrict__ h,
                                                const float* __restrict__ bias,
                                                const float* __restrict__ ro_w,
                                                const float* __restrict__ ro_b) {
    int i = blockIdx.x;
    int f = threadIdx.x;
    __shared__ int   s_row[128];
    __shared__ float s_nrm[128];
    __shared__ float sm[128];
    __shared__ float pp[16][8];
    float di = g_dinv[i];
    float acc = di * di * __half2float(h[(size_t)i * 128 + f]);
    int e0 = g_off[i], e1 = g_off[i + 1];
    for (int base = e0; base < e1; base += 128) {
        int n = min(128, e1 - base);
        if (f < n) { s_row[f] = g_erow[base + f]; s_nrm[f] = g_enorm[base + f]; }
        __syncthreads();
        #pragma unroll 4
        for (int j = 0; j < n; ++j)
            acc = fmaf(s_nrm[j], __half2float(h[(size_t)s_row[j] * 128 + f]), acc);
        __syncthreads();
    }
    sm[f] = mishf(acc + bias[f]);
    __syncthreads();
    int g2 = f >> 3, j = f & 7;
    float p = 0.0f;
    #pragma unroll
    for (int t = 0; t < 8; ++t) {
        int k = g2 * 8 + t;
        p = fmaf(sm[k], __ldg(&ro_w[k * 8 + j]), p);
    }
    pp[g2][j] = p;
    __syncthreads();
    if (f < 8) {
        float s = 0.0f;
        #pragma unroll
        for (int g = 0; g < 16; ++g) s += pp[g][f];
        g_feats[(size_t)i * 8 + f] = mishf(s + __ldg(&ro_b[f]));
    }
}

// ---------------- fc1: 2 graphs per block ----------------
__global__ __launch_bounds__(400) void k_fc1(const float* __restrict__ W,
                                             const float* __restrict__ b) {
    int g0 = blockIdx.x * 2;
    int c = threadIdx.x;
    __shared__ float s0[FC1_IN], s1[FC1_IN];
    for (int k = c; k < FC1_IN; k += FC1_OUT) {
        s0[k] = g_feats[(size_t)g0 * FC1_IN + k];
        s1[k] = g_feats[(size_t)(g0 + 1) * FC1_IN + k];
    }
    __syncthreads();
    float a0 = b[c], a1 = a0;
    #pragma unroll 4
    for (int k = 0; k < FC1_IN; ++k) {
        float w = W[(size_t)k * FC1_OUT + c];
        a0 = fmaf(s0[k], w, a0);
        a1 = fmaf(s1[k], w, a1);
    }
    g_z[g0 * FC1_OUT + c] = a0;
    g_z[(g0 + 1) * FC1_OUT + c] = a1;
}

// ---------------- batchnorm stats ----------------
__global__ void k_bn_stats() {
    int c = blockIdx.x * blockDim.x + threadIdx.x;
    if (c >= FC1_OUT) return;
    float s = 0.0f;
    for (int r = 0; r < N_GRAPHS; ++r) s += g_z[r * FC1_OUT + c];
    float m = s * (1.0f / N_GRAPHS);
    float v = 0.0f;
    for (int r = 0; r < N_GRAPHS; ++r) {
        float d = g_z[r * FC1_OUT + c] - m;
        v = fmaf(d, d, v);
    }
    v *= (1.0f / N_GRAPHS);
    g_mu[c] = m;
    g_rstd[c] = rsqrtf(v + BN_EPS);
}

// ---------------- final head ----------------
__global__ __launch_bounds__(512) void k_final(const float* __restrict__ gamma,
                                               const float* __restrict__ beta,
                                               const float* __restrict__ w2,
                                               const float* __restrict__ b2,
                                               float* __restrict__ out) {
    int g = blockIdx.x;
    int t = threadIdx.x;
    __shared__ float s0[512], s1[512];
    float v0 = 0.0f, v1 = 0.0f;
    if (t < FC1_OUT) {
        float zn = (g_z[g * FC1_OUT + t] - g_mu[t]) * g_rstd[t] * gamma[t] + beta[t];
        float m = mishf(zn);
        v0 = m * w2[t * 2 + 0];
        v1 = m * w2[t * 2 + 1];
    }
    s0[t] = v0; s1[t] = v1;
    __syncthreads();
    for (int d = 256; d > 0; d >>= 1) {
        if (t < d) { s0[t] += s0[t + d]; s1[t] += s1[t + d]; }
        __syncthreads();
    }
    if (t == 0) {
        out[g * 2 + 0] = s0[0] + b2[0];
        out[g * 2 + 1] = s1[0] + b2[1];
    }
}

// ---------------- host launcher ----------------
extern "C" void kernel_launch(void* const* d_in, const int* in_sizes, int n_in,
                              void* d_out, int out_size) {
    const float* x      = (const float*)d_in[0];
    const int*   ei     = (const int*)d_in[1];
    const float* ea     = (const float*)d_in[2];
    const float* w1     = (const float*)d_in[4];
    const float* b1     = (const float*)d_in[5];
    const float* w2     = (const float*)d_in[6];
    const float* b2     = (const float*)d_in[7];
    const float* ro_w   = (const float*)d_in[8];
    const float* ro_b   = (const float*)d_in[9];
    const float* fc1_w  = (const float*)d_in[10];
    const float* fc1_b  = (const float*)d_in[11];
    const float* gamma  = (const float*)d_in[12];
    const float* beta   = (const float*)d_in[13];
    const float* fc2_w  = (const float*)d_in[14];
    const float* fc2_b  = (const float*)d_in[15];
    float* out = (float*)d_out;

    const int* row = ei;
    const int* col = ei + N_EDGES;

    __half* pH = nullptr;
    float*  pB = nullptr;
    cudaGetSymbolAddress((void**)&pH, g_h16);
    cudaGetSymbolAddress((void**)&pB, g_bufB);

    static cudaStream_t s2 = nullptr;
    static cudaEvent_t evFork = nullptr, evJoin = nullptr;
    if (!s2) {
        cudaStreamCreateWithFlags(&s2, cudaStreamNonBlocking);
        cudaEventCreateWithFlags(&evFork, cudaEventDisableTiming);
        cudaEventCreateWithFlags(&evJoin, cudaEventDisableTiming);
    }

    // fork: preprocessing on s2 hides under GEMM1
    cudaEventRecord(evFork, 0);
    cudaStreamWaitEvent(s2, evFork, 0);

    k_init_deg_cnt<<<(N_NODES + 255) / 256, 256, 0, s2>>>();
    k_edge_pass1<<<(N_EDGES + 255) / 256, 256, 0, s2>>>(col, ea);
    k_part_dinv<<<SCAN_BLOCKS, 1024, 0, s2>>>();
    k_scan_part<<<1, 32, 0, s2>>>();
    k_scan_blocks<<<SCAN_BLOCKS, 1024, 0, s2>>>();
    k_edge_pass2<<<(N_EDGES + 255) / 256, 256, 0, s2>>>(row, col, ea);
    cudaEventRecord(evJoin, s2);

    // GEMM1 (tensor cores, concurrent with preprocessing)
    k_gemm_bf16<<<N_NODES / 128, 256>>>(x, w1, pH, F_IN);

    cudaStreamWaitEvent(0, evJoin, 0);

    // conv1 agg -> fp32; conv2 GEMM -> fp16; agg2 fused with readout
    k_agg1<<<N_NODES, 128>>>(pH, b1, pB);
    k_gemm_bf16<<<N_NODES / 128, 256>>>(pB, w2, pH, F_HID);
    k_agg2ro<<<N_NODES, 128>>>(pH, b2, ro_w, ro_b);

    // fc1 -> z [128, 400]
    k_fc1<<<N_GRAPHS / 2, FC1_OUT>>>(fc1_w, fc1_b);

    // batchnorm stats + final head
    k_bn_stats<<<2, 256>>>();
    k_final<<<N_GRAPHS, 512>>>(gamma, beta, fc2_w, fc2_b, out);
}

// round 5
// speedup vs baseline: 1.3713x; 1.1241x over previous
#include <cuda_runtime.h>
#include <cuda_fp16.h>
#include <cuda_bf16.h>
#include <mma.h>
#include <cstdint>

using namespace nvcuda;

#define N_NODES 51200
#define N_EDGES 2048000
#define F_IN    400
#define F_HID   128
#define RO_OUT  8
#define N_GRAPHS 128
#define FC1_IN  3200
#define FC1_OUT 400
#define BN_EPS  1e-5f
#define SCAN_BLOCKS 50

// ---------------- device scratch (static, allocation-free) ----------------
__device__ __half g_h16[(size_t)N_NODES * F_HID];   // GEMM output (fp16 gathers)
__device__ float  g_bufB[(size_t)N_NODES * F_HID];  // agg1 output (fp32, feeds GEMM2)
__device__ float g_deg[N_NODES];
__device__ float g_dinv[N_NODES];
__device__ int   g_cnt[N_NODES];
__device__ int   g_off[N_NODES + 1];
__device__ int   g_ptr[N_NODES];
__device__ int   g_part[SCAN_BLOCKS];
__device__ int   g_partoff[SCAN_BLOCKS];
__device__ uint2 g_edge[N_EDGES];                   // (src_row, norm bits) interleaved
__device__ float g_feats[(size_t)N_NODES * RO_OUT];
__device__ float g_z[N_GRAPHS * FC1_OUT];
__device__ float g_mu[FC1_OUT];
__device__ float g_rstd[FC1_OUT];

__device__ __forceinline__ float mishf(float x) {
    float sp = fmaxf(x, 0.0f) + log1pf(expf(-fabsf(x)));
    return x * tanhf(sp);
}

// ---------------- graph preprocessing ----------------
__global__ void k_init_deg_cnt() {
    int i = blockIdx.x * blockDim.x + threadIdx.x;
    if (i < N_NODES) { g_deg[i] = 1.0f; g_cnt[i] = 0; }
}

// 2 edges per thread
__global__ void k_edge_pass1(const int* __restrict__ col, const float* __restrict__ ew) {
    int t = blockIdx.x * blockDim.x + threadIdx.x;
    int e = t * 2;
    if (e < N_EDGES) {
        int2   c2 = *reinterpret_cast<const int2*>(&col[e]);
        float2 w2 = *reinterpret_cast<const float2*>(&ew[e]);
        atomicAdd(&g_deg[c2.x], w2.x);
        atomicAdd(&g_cnt[c2.x], 1);
        atomicAdd(&g_deg[c2.y], w2.y);
        atomicAdd(&g_cnt[c2.y], 1);
    }
}

__global__ __launch_bounds__(1024) void k_part_dinv() {
    int b = blockIdx.x, t = threadIdx.x;
    int i = b * 1024 + t;
    float d = g_deg[i];
    g_dinv[i] = (d > 0.0f) ? rsqrtf(d) : 0.0f;
    int v = g_cnt[i];
    #pragma unroll
    for (int dlt = 16; dlt > 0; dlt >>= 1) v += __shfl_down_sync(~0u, v, dlt);
    __shared__ int ws[32];
    if ((t & 31) == 0) ws[t >> 5] = v;
    __syncthreads();
    if (t < 32) {
        int x = ws[t];
        #pragma unroll
        for (int dlt = 16; dlt > 0; dlt >>= 1) x += __shfl_down_sync(~0u, x, dlt);
        if (t == 0) g_part[b] = x;
    }
}

__global__ void k_scan_part() {
    if (threadIdx.x == 0) {
        int run = 0;
        for (int b = 0; b < SCAN_BLOCKS; ++b) {
            g_partoff[b] = run;
            run += g_part[b];
        }
        g_off[N_NODES] = run;
    }
}

__global__ __launch_bounds__(1024) void k_scan_blocks() {
    int b = blockIdx.x, t = threadIdx.x;
    int i = b * 1024 + t;
    int v = g_cnt[i];
    int lane = t & 31, w = t >> 5;
    int x = v;
    #pragma unroll
    for (int dlt = 1; dlt < 32; dlt <<= 1) {
        int y = __shfl_up_sync(~0u, x, dlt);
        if (lane >= dlt) x += y;
    }
    __shared__ int ws[32];
    if (lane == 31) ws[w] = x;
    __syncthreads();
    if (w == 0) {
        int y = ws[lane];
        #pragma unroll
        for (int dlt = 1; dlt < 32; dlt <<= 1) {
            int z = __shfl_up_sync(~0u, y, dlt);
            if (lane >= dlt) y += z;
        }
        ws[lane] = y;
    }
    __syncthreads();
    int incl = x + (w > 0 ? ws[w - 1] : 0);
    int excl = incl - v + g_partoff[b];
    g_off[i] = excl;
    g_ptr[i] = excl;
}

// 2 edges per thread; fused (row, norm) record
__global__ void k_edge_pass2(const int* __restrict__ row, const int* __restrict__ col,
                             const float* __restrict__ ew) {
    int t = blockIdx.x * blockDim.x + threadIdx.x;
    int e = t * 2;
    if (e < N_EDGES) {
        int2   r2 = *reinterpret_cast<const int2*>(&row[e]);
        int2   c2 = *reinterpret_cast<const int2*>(&col[e]);
        float2 w2 = *reinterpret_cast<const float2*>(&ew[e]);
        float n0 = g_dinv[r2.x] * w2.x * g_dinv[c2.x];
        float n1 = g_dinv[r2.y] * w2.y * g_dinv[c2.y];
        int p0 = atomicAdd(&g_ptr[c2.x], 1);
        g_edge[p0] = make_uint2((unsigned)r2.x, __float_as_uint(n0));
        int p1 = atomicAdd(&g_ptr[c2.y], 1);
        g_edge[p1] = make_uint2((unsigned)r2.y, __float_as_uint(n1));
    }
}

// ---------------- bf16-split tensor-core GEMM ----------------
#define A_LD 24
#define B_LD 136
#define SM_AHI 0
#define SM_ALO (128 * A_LD * 2)
#define SM_BHI (SM_ALO + 128 * A_LD * 2)
#define SM_BLO (SM_BHI + 16 * B_LD * 2)
#define SM_TOT (SM_BLO + 16 * B_LD * 2)

__global__ __launch_bounds__(256) void k_gemm_bf16(const float* __restrict__ A,
                                                   const float* __restrict__ B,
                                                   __half* __restrict__ C, int K) {
    __shared__ __align__(16) char smem_raw[SM_TOT];
    __nv_bfloat16* Ahi = reinterpret_cast<__nv_bfloat16*>(smem_raw + SM_AHI);
    __nv_bfloat16* Alo = reinterpret_cast<__nv_bfloat16*>(smem_raw + SM_ALO);
    __nv_bfloat16* Bhi = reinterpret_cast<__nv_bfloat16*>(smem_raw + SM_BHI);
    __nv_bfloat16* Blo = reinterpret_cast<__nv_bfloat16*>(smem_raw + SM_BLO);

    int tid = threadIdx.x;
    int lane = tid & 31;
    int w = tid >> 5;
    int wm = w & 1;
    int wn = w >> 1;
    int row0 = blockIdx.x * 128;

    wmma::fragment<wmma::accumulator, 16, 16, 16, float> acc[4][2];
    #pragma unroll
    for (int i = 0; i < 4; ++i)
        #pragma unroll
        for (int j = 0; j < 2; ++j) wmma::fill_fragment(acc[i][j], 0.0f);

    for (int k0 = 0; k0 < K; k0 += 16) {
        #pragma unroll
        for (int c = 0; c < 2; ++c) {
            int idx = tid + c * 256;
            int ar = idx >> 2, kq = (idx & 3) * 4;
            float4 v = *reinterpret_cast<const float4*>(&A[(size_t)(row0 + ar) * K + k0 + kq]);
            __nv_bfloat16 hx = __float2bfloat16_rn(v.x);
            __nv_bfloat16 hy = __float2bfloat16_rn(v.y);
            __nv_bfloat16 hz = __float2bfloat16_rn(v.z);
            __nv_bfloat16 hw = __float2bfloat16_rn(v.w);
            __nv_bfloat162 h0; h0.x = hx; h0.y = hy;
            __nv_bfloat162 h1; h1.x = hz; h1.y = hw;
            __nv_bfloat162 l0; l0.x = __float2bfloat16_rn(v.x - __bfloat162float(hx));
                               l0.y = __float2bfloat16_rn(v.y - __bfloat162float(hy));
            __nv_bfloat162 l1; l1.x = __float2bfloat16_rn(v.z - __bfloat162float(hz));
                               l1.y = __float2bfloat16_rn(v.w - __bfloat162float(hw));
            __nv_bfloat16* ph = &Ahi[ar * A_LD + kq];
            __nv_bfloat16* pl = &Alo[ar * A_LD + kq];
            *reinterpret_cast<__nv_bfloat162*>(ph)     = h0;
            *reinterpret_cast<__nv_bfloat162*>(ph + 2) = h1;
            *reinterpret_cast<__nv_bfloat162*>(pl)     = l0;
            *reinterpret_cast<__nv_bfloat162*>(pl + 2) = l1;
        }
        #pragma unroll
        for (int c = 0; c < 2; ++c) {
            int idx = tid + c * 256;
            int kr = idx >> 5, cq = (idx & 31) * 4;
            float4 v = *reinterpret_cast<const float4*>(&B[(size_t)(k0 + kr) * 128 + cq]);
            __nv_bfloat16 hx = __float2bfloat16_rn(v.x);
            __nv_bfloat16 hy = __float2bfloat16_rn(v.y);
            __nv_bfloat16 hz = __float2bfloat16_rn(v.z);
            __nv_bfloat16 hw = __float2bfloat16_rn(v.w);
            __nv_bfloat162 h0; h0.x = hx; h0.y = hy;
            __nv_bfloat162 h1; h1.x = hz; h1.y = hw;
            __nv_bfloat162 l0; l0.x = __float2bfloat16_rn(v.x - __bfloat162float(hx));
                               l0.y = __float2bfloat16_rn(v.y - __bfloat162float(hy));
            __nv_bfloat162 l1; l1.x = __float2bfloat16_rn(v.z - __bfloat162float(hz));
                               l1.y = __float2bfloat16_rn(v.w - __bfloat162float(hw));
            __nv_bfloat16* ph = &Bhi[kr * B_LD + cq];
            __nv_bfloat16* pl = &Blo[kr * B_LD + cq];
            *reinterpret_cast<__nv_bfloat162*>(ph)     = h0;
            *reinterpret_cast<__nv_bfloat162*>(ph + 2) = h1;
            *reinterpret_cast<__nv_bfloat162*>(pl)     = l0;
            *reinterpret_cast<__nv_bfloat162*>(pl + 2) = l1;
        }
        __syncthreads();

        wmma::fragment<wmma::matrix_b, 16, 16, 16, __nv_bfloat16, wmma::row_major> bh[2], bl[2];
        #pragma unroll
        for (int j = 0; j < 2; ++j) {
            wmma::load_matrix_sync(bh[j], &Bhi[wn * 32 + j * 16], B_LD);
            wmma::load_matrix_sync(bl[j], &Blo[wn * 32 + j * 16], B_LD);
        }
        wmma::fragment<wmma::matrix_a, 16, 16, 16, __nv_bfloat16, wmma::row_major> af[4];
        #pragma unroll
        for (int i = 0; i < 4; ++i)
            wmma::load_matrix_sync(af[i], &Ahi[(wm * 64 + i * 16) * A_LD], A_LD);
        #pragma unroll
        for (int i = 0; i < 4; ++i)
            #pragma unroll
            for (int j = 0; j < 2; ++j) {
                wmma::mma_sync(acc[i][j], af[i], bh[j], acc[i][j]);
                wmma::mma_sync(acc[i][j], af[i], bl[j], acc[i][j]);
            }
        #pragma unroll
        for (int i = 0; i < 4; ++i)
            wmma::load_matrix_sync(af[i], &Alo[(wm * 64 + i * 16) * A_LD], A_LD);
        #pragma unroll
        for (int i = 0; i < 4; ++i)
            #pragma unroll
            for (int j = 0; j < 2; ++j)
                wmma::mma_sync(acc[i][j], af[i], bh[j], acc[i][j]);
        __syncthreads();
    }

    float* stage = reinterpret_cast<float*>(smem_raw) + w * 16 * 20;
    int r = lane >> 1, c0 = (lane & 1) * 8;
    #pragma unroll
    for (int i = 0; i < 4; ++i)
        #pragma unroll
        for (int j = 0; j < 2; ++j) {
            wmma::store_matrix_sync(stage, acc[i][j], 20, wmma::mem_row_major);
            __syncwarp();
            const float* sp = stage + r * 20 + c0;
            __half2 o[4];
            #pragma unroll
            for (int q = 0; q < 4; ++q) o[q] = __floats2half2_rn(sp[2 * q], sp[2 * q + 1]);
            size_t grow = (size_t)(row0 + wm * 64 + i * 16 + r);
            int gcol = wn * 32 + j * 16 + c0;
            *reinterpret_cast<uint4*>(&C[grow * 128 + gcol]) = *reinterpret_cast<uint4*>(o);
            __syncwarp();
        }
}

// ---------------- aggregation: 64 threads/node, half2 per thread ----------------
// agg1: out(fp32) = mish(agg + b)
__global__ __launch_bounds__(64) void k_agg1(const __half2* __restrict__ hp,
                                             const float* __restrict__ bias,
                                             float* __restrict__ out) {
    int i = blockIdx.x;
    int t = threadIdx.x;           // 0..63 : features [2t, 2t+1]
    __shared__ uint2 s_e[64];
    float di = g_dinv[i];
    float w0 = di * di;
    float2 sv = __half22float2(hp[(size_t)i * 64 + t]);
    float a0 = w0 * sv.x, a1 = w0 * sv.y;
    int e0 = g_off[i], e1 = g_off[i + 1];
    for (int base = e0; base < e1; base += 64) {
        int n = min(64, e1 - base);
        if (t < n) s_e[t] = g_edge[base + t];
        __syncthreads();
        #pragma unroll 4
        for (int j = 0; j < n; ++j) {
            uint2 e = s_e[j];
            float nrm = __uint_as_float(e.y);
            float2 v = __half22float2(hp[(size_t)e.x * 64 + t]);
            a0 = fmaf(nrm, v.x, a0);
            a1 = fmaf(nrm, v.y, a1);
        }
        __syncthreads();
    }
    float2 bb = *reinterpret_cast<const float2*>(&bias[t * 2]);
    float2 o;
    o.x = mishf(a0 + bb.x);
    o.y = mishf(a1 + bb.y);
    *reinterpret_cast<float2*>(&out[(size_t)i * 128 + t * 2]) = o;
}

// agg2 + readout fused: feats[i][0..7] = mish( mish(agg+b) @ ro_w + ro_b )
__global__ __launch_bounds__(64) void k_agg2ro(const __half2* __restrict__ hp,
                                               const float* __restrict__ bias,
                                               const float* __restrict__ ro_w,
                                               const float* __restrict__ ro_b) {
    int i = blockIdx.x;
    int t = threadIdx.x;
    int lane = t & 31, w = t >> 5;
    __shared__ uint2 s_e[64];
    __shared__ float pp[2][8];
    float di = g_dinv[i];
    float w0 = di * di;
    float2 sv = __half22float2(hp[(size_t)i * 64 + t]);
    float a0 = w0 * sv.x, a1 = w0 * sv.y;
    int e0 = g_off[i], e1 = g_off[i + 1];
    for (int base = e0; base < e1; base += 64) {
        int n = min(64, e1 - base);
        if (t < n) s_e[t] = g_edge[base + t];
        __syncthreads();
        #pragma unroll 4
        for (int j = 0; j < n; ++j) {
            uint2 e = s_e[j];
            float nrm = __uint_as_float(e.y);
            float2 v = __half22float2(hp[(size_t)e.x * 64 + t]);
            a0 = fmaf(nrm, v.x, a0);
            a1 = fmaf(nrm, v.y, a1);
        }
        __syncthreads();
    }
    float2 bb = *reinterpret_cast<const float2*>(&bias[t * 2]);
    float m0 = mishf(a0 + bb.x);
    float m1 = mishf(a1 + bb.y);
    // partials: p[j] = m0*W[2t][j] + m1*W[2t+1][j]
    const float4* wp = reinterpret_cast<const float4*>(&ro_w[t * 16]);
    float4 wa = wp[0], wb = wp[1], wc = wp[2], wd = wp[3];
    float p[8];
    p[0] = m0 * wa.x + m1 * wc.x;  p[1] = m0 * wa.y + m1 * wc.y;
    p[2] = m0 * wa.z + m1 * wc.z;  p[3] = m0 * wa.w + m1 * wc.w;
    p[4] = m0 * wb.x + m1 * wd.x;  p[5] = m0 * wb.y + m1 * wd.y;
    p[6] = m0 * wb.z + m1 * wd.z;  p[7] = m0 * wb.w + m1 * wd.w;
    #pragma unroll
    for (int j = 0; j < 8; ++j)
        #pragma unroll
        for (int d = 16; d > 0; d >>= 1)
            p[j] += __shfl_xor_sync(~0u, p[j], d);
    if (lane == 0)
        #pragma unroll
        for (int j = 0; j < 8; ++j) pp[w][j] = p[j];
    __syncthreads();
    if (t < 8)
        g_feats[(size_t)i * 8 + t] = mishf(pp[0][t] + pp[1][t] + __ldg(&ro_b[t]));
}

// ---------------- fc1: 2 graphs per block ----------------
__global__ __launch_bounds__(400) void k_fc1(const float* __restrict__ W,
                                             const float* __restrict__ b) {
    int g0 = blockIdx.x * 2;
    int c = threadIdx.x;
    __shared__ float s0[FC1_IN], s1[FC1_IN];
    for (int k = c; k < FC1_IN; k += FC1_OUT) {
        s0[k] = g_feats[(size_t)g0 * FC1_IN + k];
        s1[k] = g_feats[(size_t)(g0 + 1) * FC1_IN + k];
    }
    __syncthreads();
    float a0 = b[c], a1 = a0;
    #pragma unroll 4
    for (int k = 0; k < FC1_IN; ++k) {
        float w = W[(size_t)k * FC1_OUT + c];
        a0 = fmaf(s0[k], w, a0);
        a1 = fmaf(s1[k], w, a1);
    }
    g_z[g0 * FC1_OUT + c] = a0;
    g_z[(g0 + 1) * FC1_OUT + c] = a1;
}

// ---------------- batchnorm stats ----------------
__global__ void k_bn_stats() {
    int c = blockIdx.x * blockDim.x + threadIdx.x;
    if (c >= FC1_OUT) return;
    float s = 0.0f;
    for (int r = 0; r < N_GRAPHS; ++r) s += g_z[r * FC1_OUT + c];
    float m = s * (1.0f / N_GRAPHS);
    float v = 0.0f;
    for (int r = 0; r < N_GRAPHS; ++r) {
        float d = g_z[r * FC1_OUT + c] - m;
        v = fmaf(d, d, v);
    }
    v *= (1.0f / N_GRAPHS);
    g_mu[c] = m;
    g_rstd[c] = rsqrtf(v + BN_EPS);
}

// ---------------- final head ----------------
__global__ __launch_bounds__(512) void k_final(const float* __restrict__ gamma,
                                               const float* __restrict__ beta,
                                               const float* __restrict__ w2,
                                               const float* __restrict__ b2,
                                               float* __restrict__ out) {
    int g = blockIdx.x;
    int t = threadIdx.x;
    __shared__ float s0[512], s1[512];
    float v0 = 0.0f, v1 = 0.0f;
    if (t < FC1_OUT) {
        float zn = (g_z[g * FC1_OUT + t] - g_mu[t]) * g_rstd[t] * gamma[t] + beta[t];
        float m = mishf(zn);
        v0 = m * w2[t * 2 + 0];
        v1 = m * w2[t * 2 + 1];
    }
    s0[t] = v0; s1[t] = v1;
    __syncthreads();
    for (int d = 256; d > 0; d >>= 1) {
        if (t < d) { s0[t] += s0[t + d]; s1[t] += s1[t + d]; }
        __syncthreads();
    }
    if (t == 0) {
        out[g * 2 + 0] = s0[0] + b2[0];
        out[g * 2 + 1] = s1[0] + b2[1];
    }
}

// ---------------- host launcher ----------------
extern "C" void kernel_launch(void* const* d_in, const int* in_sizes, int n_in,
                              void* d_out, int out_size) {
    const float* x      = (const float*)d_in[0];
    const int*   ei     = (const int*)d_in[1];
    const float* ea     = (const float*)d_in[2];
    const float* w1     = (const float*)d_in[4];
    const float* b1     = (const float*)d_in[5];
    const float* w2     = (const float*)d_in[6];
    const float* b2     = (const float*)d_in[7];
    const float* ro_w   = (const float*)d_in[8];
    const float* ro_b   = (const float*)d_in[9];
    const float* fc1_w  = (const float*)d_in[10];
    const float* fc1_b  = (const float*)d_in[11];
    const float* gamma  = (const float*)d_in[12];
    const float* beta   = (const float*)d_in[13];
    const float* fc2_w  = (const float*)d_in[14];
    const float* fc2_b  = (const float*)d_in[15];
    float* out = (float*)d_out;

    const int* row = ei;
    const int* col = ei + N_EDGES;

    __half* pH = nullptr;
    float*  pB = nullptr;
    cudaGetSymbolAddress((void**)&pH, g_h16);
    cudaGetSymbolAddress((void**)&pB, g_bufB);
    __half2* pH2 = reinterpret_cast<__half2*>(pH);

    static cudaStream_t s2 = nullptr;
    static cudaEvent_t evFork = nullptr, evJoin = nullptr;
    if (!s2) {
        cudaStreamCreateWithFlags(&s2, cudaStreamNonBlocking);
        cudaEventCreateWithFlags(&evFork, cudaEventDisableTiming);
        cudaEventCreateWithFlags(&evJoin, cudaEventDisableTiming);
    }

    // fork: preprocessing on s2 hides under GEMM1
    cudaEventRecord(evFork, 0);
    cudaStreamWaitEvent(s2, evFork, 0);

    k_init_deg_cnt<<<(N_NODES + 255) / 256, 256, 0, s2>>>();
    k_edge_pass1<<<(N_EDGES / 2 + 255) / 256, 256, 0, s2>>>(col, ea);
    k_part_dinv<<<SCAN_BLOCKS, 1024, 0, s2>>>();
    k_scan_part<<<1, 32, 0, s2>>>();
    k_scan_blocks<<<SCAN_BLOCKS, 1024, 0, s2>>>();
    k_edge_pass2<<<(N_EDGES / 2 + 255) / 256, 256, 0, s2>>>(row, col, ea);
    cudaEventRecord(evJoin, s2);

    // GEMM1 (tensor cores, concurrent with preprocessing)
    k_gemm_bf16<<<N_NODES / 128, 256>>>(x, w1, pH, F_IN);

    cudaStreamWaitEvent(0, evJoin, 0);

    // conv1 agg -> fp32; conv2 GEMM -> fp16; agg2 fused with readout
    k_agg1<<<N_NODES, 64>>>(pH2, b1, pB);
    k_gemm_bf16<<<N_NODES / 128, 256>>>(pB, w2, pH, F_HID);
    k_agg2ro<<<N_NODES, 64>>>(pH2, b2, ro_w, ro_b);

    // fc1 -> z [128, 400]
    k_fc1<<<N_GRAPHS / 2, FC1_OUT>>>(fc1_w, fc1_b);

    // batchnorm stats + final head
    k_bn_stats<<<2, 256>>>();
    k_final<<<N_GRAPHS, 512>>>(gamma, beta, fc2_w, fc2_b, out);
}